// round 12
// baseline (speedup 1.0000x reference)
#include <cuda_runtime.h>
#include <cuda_fp16.h>
#include <cstdint>

#define H 128

// ---------------------------------------------------------------------------
// Global scratch (no allocations allowed)
// ---------------------------------------------------------------------------
// Per-node layer-1 partials in fp16: [gd_gene | gd_dis | gg_src | gg_dst]
__device__ __half g_Ph[42000000];
// fp16 weights, transposed [part][n][k]  (for the tensor-warp region)
__device__ __half g_Wh[4 * H * H];
// fp16 weights, k-major [part][k][32] — columns 96..127 only (SIMT region)
__device__ __half g_Wk[4 * H * 32];

// ---------------------------------------------------------------------------
// helpers
// ---------------------------------------------------------------------------
__device__ __forceinline__ uint32_t smem_u32(const void* p){
    uint32_t a;
    asm("{ .reg .u64 t; cvta.to.shared.u64 t, %1; cvt.u32.u64 %0, t; }" : "=r"(a) : "l"(p));
    return a;
}
__device__ __forceinline__ void ldsm4(uint32_t* r, uint32_t addr){
    asm volatile("ldmatrix.sync.aligned.m8n8.x4.shared.b16 {%0,%1,%2,%3}, [%4];"
        : "=r"(r[0]), "=r"(r[1]), "=r"(r[2]), "=r"(r[3]) : "r"(addr));
}
__device__ __forceinline__ void mma_f16(float* d, const uint32_t* a,
                                        uint32_t b0, uint32_t b1){
    asm volatile("mma.sync.aligned.m16n8k16.row.col.f32.f16.f16.f32 "
        "{%0,%1,%2,%3}, {%4,%5,%6,%7}, {%8,%9}, {%0,%1,%2,%3};"
        : "+f"(d[0]), "+f"(d[1]), "+f"(d[2]), "+f"(d[3])
        : "r"(a[0]), "r"(a[1]), "r"(a[2]), "r"(a[3]), "r"(b0), "r"(b1));
}

// XOR-swizzled byte offset inside a [128 rows x 128 fp16] tile (256B rows).
__device__ __forceinline__ uint32_t toff(int r, int kc){
    return (uint32_t)r * 256u + (uint32_t)((kc ^ (r & 7)) << 4);
}

// smem map: A 32KB | B 32KB | B_T (k-major, cols 96..127) 8KB
#define SM_A  0
#define SM_B  32768
#define SM_BT 65536
#define SM_TOTAL 73728

// ---------------------------------------------------------------------------
// Kernel 0: round the four 128x128 W blocks -> fp16:
//   g_Wh[part][n][k] (transposed)  and  g_Wk[part][k][n-96] for n in 96..127
// ---------------------------------------------------------------------------
__global__ void prep_w_kernel(const float* __restrict__ w1_gd,
                              const float* __restrict__ w1_gg)
{
    int idx = blockIdx.x * blockDim.x + threadIdx.x;  // 4*128*128
    if (idx >= 4 * H * H) return;
    int part = idx >> 14;
    int n = (idx >> 7) & 127;
    int k = idx & 127;
    const float* Wsrc = (part == 0) ? w1_gd
                      : (part == 1) ? w1_gg
                      : (part == 2) ? (w1_gg + H * H)
                                    : (w1_gd + H * H);
    __half v = __float2half_rn(Wsrc[k * H + n]);
    g_Wh[((size_t)part * H + n) * H + k] = v;
    if (n >= 96)
        g_Wk[((size_t)part * H + k) * 32 + (n - 96)] = v;
}

// ---------------------------------------------------------------------------
// Kernel 1: HYBRID GEMM. 512 threads:
//   warps 0..11 : HMMA, cols 0..95  (4 row-warps x 3 col-warps, 32x32 tiles)
//   warps 12..15: SIMT HFMA2, cols 96..127 (one 32-row band each) — runs on
//                 the otherwise-idle fma pipe, +50% MAC rate.
// A staged once; gene tiles loop parts 0,1,2; disease tiles part 3.
// ---------------------------------------------------------------------------
__global__ void __launch_bounds__(512, 2)
gemm_tc_kernel(const float* __restrict__ zg, const float* __restrict__ zd,
               const float* __restrict__ b1_gd, const float* __restrict__ b1_gg,
               int n_gene, int n_dis)
{
    extern __shared__ char smem[];
    const uint32_t sb = smem_u32(smem);
    const int tid = threadIdx.x;

    const int tg = (n_gene + 127) >> 7;
    const size_t ng = (size_t)n_gene * H, nd = (size_t)n_dis * H;

    const int b = blockIdx.x;
    const bool isGene = (b < tg);
    const float* A = isGene ? zg : zd;
    const int M = isGene ? n_gene : n_dis;
    const int m0 = (isGene ? b : (b - tg)) << 7;
    const int nparts = isGene ? 3 : 1;

    // ---- stage A (fp32 -> fp16) once: 2048 16B chunks, 4 per thread ----
    #pragma unroll
    for (int i = 0; i < 4; i++) {
        int u = tid + 512 * i;
        int r = u >> 4, c8 = u & 15;
        float4 v0 = make_float4(0.f,0.f,0.f,0.f), v1 = v0;
        if (m0 + r < M) {
            const float* ap = &A[(size_t)(m0 + r) * H + c8 * 8];
            v0 = *(const float4*)ap;
            v1 = *(const float4*)(ap + 4);
        }
        __half2 h0 = __floats2half2_rn(v0.x, v0.y);
        __half2 h1 = __floats2half2_rn(v0.z, v0.w);
        __half2 h2 = __floats2half2_rn(v1.x, v1.y);
        __half2 h3 = __floats2half2_rn(v1.z, v1.w);
        uint4 pk = make_uint4(*(uint32_t*)&h0, *(uint32_t*)&h1,
                              *(uint32_t*)&h2, *(uint32_t*)&h3);
        *(uint4*)(smem + SM_A + toff(r, c8)) = pk;
    }

    const int lane = tid & 31, w = tid >> 5;
    // tensor-warp constants (valid for w<12)
    const int wr  = w & 3, wcT = w >> 2;
    const int arow = wr * 32 + (lane & 15);
    const int akh  = lane >> 4;
    const int brow = wcT * 32 + (lane & 7) + ((lane >> 4) << 3);
    const int bkh  = (lane >> 3) & 1;
    const int rbase = m0 + wr * 32 + (lane >> 2);
    const int cbase = wcT * 32 + (lane & 3) * 2;
    // SIMT-warp constants (valid for w>=12)
    const int wr2  = w - 12;
    const int rpos = lane & 7;      // 8 row positions, 4 rows each
    const int cpos = lane >> 3;     // 4 col positions; col-pairs cpos*2 + 8j

    for (int p = 0; p < nparts; p++) {
        const int part = isGene ? p : 3;
        const float* bias = (part == 2) ? b1_gg : (part == 3) ? b1_gd : nullptr;
        const size_t outOff = (part == 0) ? 0
                            : (part == 1) ? (ng + nd)
                            : (part == 2) ? (ng + nd + ng)
                                          : ng;

        // ---- stage B [n][k] (2048 chunks) + B_T [k][32] (512 chunks) ----
        {
            const uint4* bp = (const uint4*)(g_Wh + (size_t)part * H * H);
            #pragma unroll
            for (int i = 0; i < 4; i++) {
                int u = tid + 512 * i;
                int r = u >> 4, kc = u & 15;
                *(uint4*)(smem + SM_B + toff(r, kc)) = bp[u];
            }
            const uint4* bt = (const uint4*)(g_Wk + (size_t)part * H * 32);
            *(uint4*)(smem + SM_BT + tid * 16) = bt[tid];   // k = tid>>2, c4 = tid&3
        }
        __syncthreads();

        if (w < 12) {
            // ================= tensor path: cols 0..95 =================
            float acc[2][4][4];
            #pragma unroll
            for (int mt = 0; mt < 2; mt++)
                #pragma unroll
                for (int nt = 0; nt < 4; nt++)
                    #pragma unroll
                    for (int q = 0; q < 4; q++) acc[mt][nt][q] = 0.f;

            #pragma unroll
            for (int s = 0; s < 8; s++) {
                uint32_t afr[2][4];
                #pragma unroll
                for (int mt = 0; mt < 2; mt++)
                    ldsm4(afr[mt], sb + SM_A + toff(arow + mt * 16, 2 * s + akh));
                uint32_t bfr[2][4];
                #pragma unroll
                for (int np = 0; np < 2; np++)
                    ldsm4(bfr[np], sb + SM_B + toff(brow + np * 16, 2 * s + bkh));
                #pragma unroll
                for (int mt = 0; mt < 2; mt++)
                    #pragma unroll
                    for (int nt = 0; nt < 4; nt++)
                        mma_f16(acc[mt][nt], afr[mt],
                                bfr[nt >> 1][(nt & 1) * 2], bfr[nt >> 1][(nt & 1) * 2 + 1]);
            }

            #pragma unroll
            for (int mt = 0; mt < 2; mt++) {
                #pragma unroll
                for (int nt = 0; nt < 4; nt++) {
                    int n = cbase + nt * 8;
                    float bx = 0.f, by = 0.f;
                    if (bias) { float2 bv = *(const float2*)&bias[n]; bx = bv.x; by = bv.y; }
                    int rr0 = rbase + mt * 16;
                    int rr1 = rr0 + 8;
                    if (rr0 < M) {
                        __half2 o0 = __floats2half2_rn(acc[mt][nt][0] + bx, acc[mt][nt][1] + by);
                        *(__half2*)&g_Ph[outOff + (size_t)rr0 * H + n] = o0;
                    }
                    if (rr1 < M) {
                        __half2 o1 = __floats2half2_rn(acc[mt][nt][2] + bx, acc[mt][nt][3] + by);
                        *(__half2*)&g_Ph[outOff + (size_t)rr1 * H + n] = o1;
                    }
                }
            }
        } else {
            // ================= SIMT path: cols 96..127 =================
            // thread: rows wr2*32 + rpos*4 + {0..3}; col-pairs 96 + cpos*2 + 8j
            __half2 acc[4][4];
            #pragma unroll
            for (int i = 0; i < 4; i++)
                #pragma unroll
                for (int j = 0; j < 4; j++) acc[i][j] = __half2half2(__ushort_as_half(0));

            const int r0 = wr2 * 32 + rpos * 4;
            for (int kb = 0; kb < 16; kb++) {          // 16 blocks of 8 k
                uint4 araw[4];
                #pragma unroll
                for (int i = 0; i < 4; i++)
                    araw[i] = *(uint4*)(smem + SM_A + toff(r0 + i, kb));
                #pragma unroll
                for (int kk = 0; kk < 8; kk++) {
                    const __half2* bt = (const __half2*)(smem + SM_BT
                                        + (kb * 8 + kk) * 64 + cpos * 4);
                    __half2 b0 = bt[0], b1 = bt[4], b2 = bt[8], b3 = bt[12];
                    #pragma unroll
                    for (int i = 0; i < 4; i++) {
                        uint32_t q = (&araw[i].x)[kk >> 1];
                        __half2 av = *(__half2*)&q;
                        __half2 ad = (kk & 1) ? __high2half2(av) : __low2half2(av);
                        acc[i][0] = __hfma2(ad, b0, acc[i][0]);
                        acc[i][1] = __hfma2(ad, b1, acc[i][1]);
                        acc[i][2] = __hfma2(ad, b2, acc[i][2]);
                        acc[i][3] = __hfma2(ad, b3, acc[i][3]);
                    }
                }
            }

            #pragma unroll
            for (int i = 0; i < 4; i++) {
                int row = m0 + r0 + i;
                if (row < M) {
                    #pragma unroll
                    for (int j = 0; j < 4; j++) {
                        int n = 96 + cpos * 2 + 8 * j;
                        float2 v = __half22float2(acc[i][j]);
                        if (bias) { float2 bv = *(const float2*)&bias[n];
                                    v.x += bv.x; v.y += bv.y; }
                        *(__half2*)&g_Ph[outOff + (size_t)row * H + n] =
                            __floats2half2_rn(v.x, v.y);
                    }
                }
            }
        }
        if (p + 1 < nparts) __syncthreads();
    }
}

// ---------------------------------------------------------------------------
// Kernel 2: per-edge combine on fp16 partials. One warp per edge, x2 ILP.
// ---------------------------------------------------------------------------
__global__ void __launch_bounds__(256)
edge_decode_kernel(const int* __restrict__ edges_gd, const int* __restrict__ edges_gg,
                   const float* __restrict__ w2_gd, const float* __restrict__ b2_gd,
                   const float* __restrict__ w2_gg, const float* __restrict__ b2_gg,
                   float* __restrict__ out, int E, int n_gene, int n_dis)
{
    const int rel = blockIdx.y;
    const size_t ng = (size_t)n_gene * H;
    const size_t nd = (size_t)n_dis * H;

    const int*   edges = rel ? edges_gg : edges_gd;
    const __half* Psrc = rel ? (g_Ph + ng + nd)      : g_Ph;
    const __half* Pdst = rel ? (g_Ph + ng + nd + ng) : (g_Ph + ng);
    const float* w2    = rel ? w2_gg : w2_gd;
    const float  b2    = (rel ? b2_gg : b2_gd)[0];
    float* o = out + (size_t)rel * E;

    const int lane   = threadIdx.x & 31;
    const int warp   = (blockIdx.x * blockDim.x + threadIdx.x) >> 5;
    const int nwarps = (gridDim.x * blockDim.x) >> 5;

    const float4 w = *(const float4*)&w2[lane * 4];

    for (int e = warp; e < E; e += 2 * nwarps) {
        const int e1 = e + nwarps;
        const bool has2 = e1 < E;

        const int s0 = edges[e], d0 = edges[E + e];
        uint2 ua0 = *(const uint2*)&Psrc[(size_t)s0 * H + lane * 4];
        uint2 ub0 = *(const uint2*)&Pdst[(size_t)d0 * H + lane * 4];

        uint2 ua1 = make_uint2(0u, 0u), ub1 = ua1;
        if (has2) {
            const int s1 = edges[e1], d1 = edges[E + e1];
            ua1 = *(const uint2*)&Psrc[(size_t)s1 * H + lane * 4];
            ub1 = *(const uint2*)&Pdst[(size_t)d1 * H + lane * 4];
        }

        float2 fa0 = __half22float2(*(__half2*)&ua0.x);
        float2 fa1 = __half22float2(*(__half2*)&ua0.y);
        float2 fb0 = __half22float2(*(__half2*)&ub0.x);
        float2 fb1 = __half22float2(*(__half2*)&ub0.y);
        float sum0;
        sum0  = fmaxf(fa0.x + fb0.x, 0.f) * w.x;
        sum0 += fmaxf(fa0.y + fb0.y, 0.f) * w.y;
        sum0 += fmaxf(fa1.x + fb1.x, 0.f) * w.z;
        sum0 += fmaxf(fa1.y + fb1.y, 0.f) * w.w;
        #pragma unroll
        for (int off = 16; off; off >>= 1)
            sum0 += __shfl_xor_sync(0xFFFFFFFFu, sum0, off);
        if (lane == 0) o[e] = sum0 + b2;

        if (has2) {
            float2 ga0 = __half22float2(*(__half2*)&ua1.x);
            float2 ga1 = __half22float2(*(__half2*)&ua1.y);
            float2 gb0 = __half22float2(*(__half2*)&ub1.x);
            float2 gb1 = __half22float2(*(__half2*)&ub1.y);
            float sum1;
            sum1  = fmaxf(ga0.x + gb0.x, 0.f) * w.x;
            sum1 += fmaxf(ga0.y + gb0.y, 0.f) * w.y;
            sum1 += fmaxf(ga1.x + gb1.x, 0.f) * w.z;
            sum1 += fmaxf(ga1.y + gb1.y, 0.f) * w.w;
            #pragma unroll
            for (int off = 16; off; off >>= 1)
                sum1 += __shfl_xor_sync(0xFFFFFFFFu, sum1, off);
            if (lane == 0) o[e1] = sum1 + b2;
        }
    }
}

// ---------------------------------------------------------------------------
extern "C" void kernel_launch(void* const* d_in, const int* in_sizes, int n_in,
                              void* d_out, int out_size)
{
    const float* z_gene = (const float*)d_in[0];
    const float* z_dis  = (const float*)d_in[1];
    const int*   e_gd   = (const int*)  d_in[2];
    const int*   e_gg   = (const int*)  d_in[3];
    const float* w1_gd  = (const float*)d_in[4];
    const float* b1_gd  = (const float*)d_in[5];
    const float* w2_gd  = (const float*)d_in[6];
    const float* b2_gd  = (const float*)d_in[7];
    const float* w1_gg  = (const float*)d_in[8];
    const float* b1_gg  = (const float*)d_in[9];
    const float* w2_gg  = (const float*)d_in[10];
    const float* b2_gg  = (const float*)d_in[11];

    const int n_gene = in_sizes[0] / H;
    const int n_dis  = in_sizes[1] / H;
    const int E      = in_sizes[2] / 2;

    static bool init_done = false;
    if (!init_done) {
        cudaFuncSetAttribute(gemm_tc_kernel,
                             cudaFuncAttributeMaxDynamicSharedMemorySize, SM_TOTAL);
        init_done = true;
    }

    prep_w_kernel<<<(4 * H * H + 255) / 256, 256>>>(w1_gd, w1_gg);

    const int tg = (n_gene + 127) >> 7;
    const int td = (n_dis + 127) >> 7;
    gemm_tc_kernel<<<tg + td, 512, SM_TOTAL>>>(z_gene, z_dis, b1_gd, b1_gg,
                                               n_gene, n_dis);

    dim3 egrid(1184, 2);
    edge_decode_kernel<<<egrid, 256>>>(e_gd, e_gg, w2_gd, b2_gd, w2_gg, b2_gg,
                                       (float*)d_out, E, n_gene, n_dis);
}

// round 13
// speedup vs baseline: 1.4120x; 1.4120x over previous
#include <cuda_runtime.h>
#include <cuda_fp16.h>
#include <cstdint>

#define H 128

// ---------------------------------------------------------------------------
// Global scratch (no allocations allowed)
// ---------------------------------------------------------------------------
// Per-node layer-1 partials in fp16: [gd_gene | gd_dis | gg_src | gg_dst]
__device__ __half g_Ph[42000000];
// fp16 weights (rounded), transposed: [part][n][k]
// part: 0 = w1_gd[:128], 1 = w1_gg[:128], 2 = w1_gg[128:], 3 = w1_gd[128:]
__device__ __half g_Wh[4 * H * H];

// ---------------------------------------------------------------------------
// helpers
// ---------------------------------------------------------------------------
__device__ __forceinline__ uint32_t smem_u32(const void* p){
    uint32_t a;
    asm("{ .reg .u64 t; cvta.to.shared.u64 t, %1; cvt.u32.u64 %0, t; }" : "=r"(a) : "l"(p));
    return a;
}
__device__ __forceinline__ void ldsm4(uint32_t* r, uint32_t addr){
    asm volatile("ldmatrix.sync.aligned.m8n8.x4.shared.b16 {%0,%1,%2,%3}, [%4];"
        : "=r"(r[0]), "=r"(r[1]), "=r"(r[2]), "=r"(r[3]) : "r"(addr));
}
__device__ __forceinline__ void mma_f16(float* d, const uint32_t* a,
                                        uint32_t b0, uint32_t b1){
    asm volatile("mma.sync.aligned.m16n8k16.row.col.f32.f16.f16.f32 "
        "{%0,%1,%2,%3}, {%4,%5,%6,%7}, {%8,%9}, {%0,%1,%2,%3};"
        : "+f"(d[0]), "+f"(d[1]), "+f"(d[2]), "+f"(d[3])
        : "r"(a[0]), "r"(a[1]), "r"(a[2]), "r"(a[3]), "r"(b0), "r"(b1));
}

// XOR-swizzled byte offset inside a [128 rows x 128 fp16] tile (256B rows).
__device__ __forceinline__ uint32_t toff(int r, int kc){
    return (uint32_t)r * 256u + (uint32_t)((kc ^ (r & 7)) << 4);
}

// smem map: A 32KB | B 32KB
#define SM_A  0
#define SM_B  32768
#define SM_TOTAL 65536

// ---------------------------------------------------------------------------
// Kernel 0: round+transpose the four 128x128 W blocks -> fp16, [n][k].
// 32x32 smem-tile transpose: coalesced reads AND writes.
// grid = 4 parts * 16 tiles = 64 blocks, 256 threads.
// ---------------------------------------------------------------------------
__global__ void prep_w_kernel(const float* __restrict__ w1_gd,
                              const float* __restrict__ w1_gg)
{
    __shared__ float t[32][33];
    const int part = blockIdx.x >> 4;
    const int tr = (blockIdx.x >> 2) & 3;   // k block
    const int tc = blockIdx.x & 3;          // n block
    const float* Wsrc = (part == 0) ? w1_gd
                      : (part == 1) ? w1_gg
                      : (part == 2) ? (w1_gg + H * H)
                                    : (w1_gd + H * H);
    const int k0 = tr * 32, n0 = tc * 32;
    const int tid = threadIdx.x;
    const int r  = tid >> 3;          // 0..31
    const int c4 = (tid & 7) * 4;     // 0,4,..,28

    // coalesced read: row k0+r, 4 consecutive n
    float4 v = *(const float4*)&Wsrc[(size_t)(k0 + r) * H + n0 + c4];
    t[r][c4 + 0] = v.x; t[r][c4 + 1] = v.y;
    t[r][c4 + 2] = v.z; t[r][c4 + 3] = v.w;
    __syncthreads();

    // transposed write: row n0+r of g_Wh, 4 consecutive k
    __half2 h0 = __floats2half2_rn(t[c4 + 0][r], t[c4 + 1][r]);
    __half2 h1 = __floats2half2_rn(t[c4 + 2][r], t[c4 + 3][r]);
    uint2 pk = make_uint2(*(uint32_t*)&h0, *(uint32_t*)&h1);
    *(uint2*)&g_Wh[((size_t)part * H + n0 + r) * H + k0 + c4] = pk;
}

// ---------------------------------------------------------------------------
// Kernel 1: single-pass fp16 GEMM (fp32 acc), 512 threads, 16 warps x 32x32.
// A staged once; gene tiles loop parts 0,1,2; disease tiles part 3.
// Part-0 B prefetched into registers before A staging (hides first B LDG).
// ---------------------------------------------------------------------------
__global__ void __launch_bounds__(512, 2)
gemm_tc_kernel(const float* __restrict__ zg, const float* __restrict__ zd,
               const float* __restrict__ b1_gd, const float* __restrict__ b1_gg,
               int n_gene, int n_dis)
{
    extern __shared__ char smem[];
    const uint32_t sb = smem_u32(smem);
    const int tid = threadIdx.x;

    const int tg = (n_gene + 127) >> 7;
    const size_t ng = (size_t)n_gene * H, nd = (size_t)n_dis * H;

    const int b = blockIdx.x;
    const bool isGene = (b < tg);
    const float* A = isGene ? zg : zd;
    const int M = isGene ? n_gene : n_dis;
    const int m0 = (isGene ? b : (b - tg)) << 7;
    const int nparts = isGene ? 3 : 1;
    const int part0 = isGene ? 0 : 3;

    // ---- prefetch part-0 B into registers (overlaps with A staging) ----
    uint4 bpre[4];
    {
        const uint4* bp = (const uint4*)(g_Wh + (size_t)part0 * H * H);
        #pragma unroll
        for (int i = 0; i < 4; i++) bpre[i] = bp[tid + 512 * i];
    }

    // ---- stage A (fp32 -> fp16) once: 2048 16B chunks, 4 per thread ----
    #pragma unroll
    for (int i = 0; i < 4; i++) {
        int u = tid + 512 * i;
        int r = u >> 4, c8 = u & 15;
        float4 v0 = make_float4(0.f,0.f,0.f,0.f), v1 = v0;
        if (m0 + r < M) {
            const float* ap = &A[(size_t)(m0 + r) * H + c8 * 8];
            v0 = *(const float4*)ap;
            v1 = *(const float4*)(ap + 4);
        }
        __half2 h0 = __floats2half2_rn(v0.x, v0.y);
        __half2 h1 = __floats2half2_rn(v0.z, v0.w);
        __half2 h2 = __floats2half2_rn(v1.x, v1.y);
        __half2 h3 = __floats2half2_rn(v1.z, v1.w);
        uint4 pk = make_uint4(*(uint32_t*)&h0, *(uint32_t*)&h1,
                              *(uint32_t*)&h2, *(uint32_t*)&h3);
        *(uint4*)(smem + SM_A + toff(r, c8)) = pk;
    }

    const int lane = tid & 31, w = tid >> 5;
    const int wr = w >> 2, wc = w & 3;          // 4x4 warp grid, 32x32 tiles
    const int arow = wr * 32 + (lane & 15);
    const int akh  = lane >> 4;
    const int brow = wc * 32 + (lane & 7) + ((lane >> 4) << 3);
    const int bkh  = (lane >> 3) & 1;
    const int rbase = m0 + wr * 32 + (lane >> 2);
    const int cbase = wc * 32 + (lane & 3) * 2;

    for (int p = 0; p < nparts; p++) {
        const int part = isGene ? p : 3;
        const float* bias = (part == 2) ? b1_gg : (part == 3) ? b1_gd : nullptr;
        const size_t outOff = (part == 0) ? 0
                            : (part == 1) ? (ng + nd)
                            : (part == 2) ? (ng + nd + ng)
                                          : ng;

        // ---- stage B for this part: 2048 chunks, 4 per thread ----
        if (p == 0) {
            #pragma unroll
            for (int i = 0; i < 4; i++) {
                int u = tid + 512 * i;
                int r = u >> 4, kc = u & 15;
                *(uint4*)(smem + SM_B + toff(r, kc)) = bpre[i];
            }
        } else {
            const uint4* bp = (const uint4*)(g_Wh + (size_t)part * H * H);
            #pragma unroll
            for (int i = 0; i < 4; i++) {
                int u = tid + 512 * i;
                int r = u >> 4, kc = u & 15;
                *(uint4*)(smem + SM_B + toff(r, kc)) = bp[u];
            }
        }
        __syncthreads();

        // ---- compute: 32x32 warp tile ----
        float acc[2][4][4];
        #pragma unroll
        for (int mt = 0; mt < 2; mt++)
            #pragma unroll
            for (int nt = 0; nt < 4; nt++)
                #pragma unroll
                for (int q = 0; q < 4; q++) acc[mt][nt][q] = 0.f;

        #pragma unroll
        for (int s = 0; s < 8; s++) {
            uint32_t afr[2][4];
            #pragma unroll
            for (int mt = 0; mt < 2; mt++)
                ldsm4(afr[mt], sb + SM_A + toff(arow + mt * 16, 2 * s + akh));

            uint32_t bfr[2][4];
            #pragma unroll
            for (int np = 0; np < 2; np++)
                ldsm4(bfr[np], sb + SM_B + toff(brow + np * 16, 2 * s + bkh));

            #pragma unroll
            for (int mt = 0; mt < 2; mt++)
                #pragma unroll
                for (int nt = 0; nt < 4; nt++)
                    mma_f16(acc[mt][nt], afr[mt],
                            bfr[nt >> 1][(nt & 1) * 2], bfr[nt >> 1][(nt & 1) * 2 + 1]);
        }

        // ---- writeout (fp16) ----
        #pragma unroll
        for (int mt = 0; mt < 2; mt++) {
            #pragma unroll
            for (int nt = 0; nt < 4; nt++) {
                int n = cbase + nt * 8;
                float bx = 0.f, by = 0.f;
                if (bias) { float2 bv = *(const float2*)&bias[n]; bx = bv.x; by = bv.y; }
                int rr0 = rbase + mt * 16;
                int rr1 = rr0 + 8;
                if (rr0 < M) {
                    __half2 o0 = __floats2half2_rn(acc[mt][nt][0] + bx, acc[mt][nt][1] + by);
                    *(__half2*)&g_Ph[outOff + (size_t)rr0 * H + n] = o0;
                }
                if (rr1 < M) {
                    __half2 o1 = __floats2half2_rn(acc[mt][nt][2] + bx, acc[mt][nt][3] + by);
                    *(__half2*)&g_Ph[outOff + (size_t)rr1 * H + n] = o1;
                }
            }
        }
        if (p + 1 < nparts) __syncthreads();
    }
}

// ---------------------------------------------------------------------------
// Kernel 2: per-edge combine on fp16 partials. One warp per edge, x2 ILP.
// ---------------------------------------------------------------------------
__global__ void __launch_bounds__(256)
edge_decode_kernel(const int* __restrict__ edges_gd, const int* __restrict__ edges_gg,
                   const float* __restrict__ w2_gd, const float* __restrict__ b2_gd,
                   const float* __restrict__ w2_gg, const float* __restrict__ b2_gg,
                   float* __restrict__ out, int E, int n_gene, int n_dis)
{
    const int rel = blockIdx.y;
    const size_t ng = (size_t)n_gene * H;
    const size_t nd = (size_t)n_dis * H;

    const int*   edges = rel ? edges_gg : edges_gd;
    const __half* Psrc = rel ? (g_Ph + ng + nd)      : g_Ph;
    const __half* Pdst = rel ? (g_Ph + ng + nd + ng) : (g_Ph + ng);
    const float* w2    = rel ? w2_gg : w2_gd;
    const float  b2    = (rel ? b2_gg : b2_gd)[0];
    float* o = out + (size_t)rel * E;

    const int lane   = threadIdx.x & 31;
    const int warp   = (blockIdx.x * blockDim.x + threadIdx.x) >> 5;
    const int nwarps = (gridDim.x * blockDim.x) >> 5;

    const float4 w = *(const float4*)&w2[lane * 4];

    for (int e = warp; e < E; e += 2 * nwarps) {
        const int e1 = e + nwarps;
        const bool has2 = e1 < E;

        const int s0 = edges[e], d0 = edges[E + e];
        uint2 ua0 = *(const uint2*)&Psrc[(size_t)s0 * H + lane * 4];
        uint2 ub0 = *(const uint2*)&Pdst[(size_t)d0 * H + lane * 4];

        uint2 ua1 = make_uint2(0u, 0u), ub1 = ua1;
        if (has2) {
            const int s1 = edges[e1], d1 = edges[E + e1];
            ua1 = *(const uint2*)&Psrc[(size_t)s1 * H + lane * 4];
            ub1 = *(const uint2*)&Pdst[(size_t)d1 * H + lane * 4];
        }

        float2 fa0 = __half22float2(*(__half2*)&ua0.x);
        float2 fa1 = __half22float2(*(__half2*)&ua0.y);
        float2 fb0 = __half22float2(*(__half2*)&ub0.x);
        float2 fb1 = __half22float2(*(__half2*)&ub0.y);
        float sum0;
        sum0  = fmaxf(fa0.x + fb0.x, 0.f) * w.x;
        sum0 += fmaxf(fa0.y + fb0.y, 0.f) * w.y;
        sum0 += fmaxf(fa1.x + fb1.x, 0.f) * w.z;
        sum0 += fmaxf(fa1.y + fb1.y, 0.f) * w.w;
        #pragma unroll
        for (int off = 16; off; off >>= 1)
            sum0 += __shfl_xor_sync(0xFFFFFFFFu, sum0, off);
        if (lane == 0) o[e] = sum0 + b2;

        if (has2) {
            float2 ga0 = __half22float2(*(__half2*)&ua1.x);
            float2 ga1 = __half22float2(*(__half2*)&ua1.y);
            float2 gb0 = __half22float2(*(__half2*)&ub1.x);
            float2 gb1 = __half22float2(*(__half2*)&ub1.y);
            float sum1;
            sum1  = fmaxf(ga0.x + gb0.x, 0.f) * w.x;
            sum1 += fmaxf(ga0.y + gb0.y, 0.f) * w.y;
            sum1 += fmaxf(ga1.x + gb1.x, 0.f) * w.z;
            sum1 += fmaxf(ga1.y + gb1.y, 0.f) * w.w;
            #pragma unroll
            for (int off = 16; off; off >>= 1)
                sum1 += __shfl_xor_sync(0xFFFFFFFFu, sum1, off);
            if (lane == 0) o[e1] = sum1 + b2;
        }
    }
}

// ---------------------------------------------------------------------------
extern "C" void kernel_launch(void* const* d_in, const int* in_sizes, int n_in,
                              void* d_out, int out_size)
{
    const float* z_gene = (const float*)d_in[0];
    const float* z_dis  = (const float*)d_in[1];
    const int*   e_gd   = (const int*)  d_in[2];
    const int*   e_gg   = (const int*)  d_in[3];
    const float* w1_gd  = (const float*)d_in[4];
    const float* b1_gd  = (const float*)d_in[5];
    const float* w2_gd  = (const float*)d_in[6];
    const float* b2_gd  = (const float*)d_in[7];
    const float* w1_gg  = (const float*)d_in[8];
    const float* b1_gg  = (const float*)d_in[9];
    const float* w2_gg  = (const float*)d_in[10];
    const float* b2_gg  = (const float*)d_in[11];

    const int n_gene = in_sizes[0] / H;
    const int n_dis  = in_sizes[1] / H;
    const int E      = in_sizes[2] / 2;

    static bool init_done = false;
    if (!init_done) {
        cudaFuncSetAttribute(gemm_tc_kernel,
                             cudaFuncAttributeMaxDynamicSharedMemorySize, SM_TOTAL);
        init_done = true;
    }

    prep_w_kernel<<<64, 256>>>(w1_gd, w1_gg);

    const int tg = (n_gene + 127) >> 7;
    const int td = (n_dis + 127) >> 7;
    gemm_tc_kernel<<<tg + td, 512, SM_TOTAL>>>(z_gene, z_dis, b1_gd, b1_gg,
                                               n_gene, n_dis);

    dim3 egrid(1184, 2);
    edge_decode_kernel<<<egrid, 256>>>(e_gd, e_gg, w2_gd, b2_gd, w2_gg, b2_gg,
                                       (float*)d_out, E, n_gene, n_dis);
}

// round 14
// speedup vs baseline: 1.4453x; 1.0235x over previous
#include <cuda_runtime.h>
#include <cuda_fp16.h>
#include <cstdint>

#define H 128

// ---------------------------------------------------------------------------
// Global scratch (no allocations allowed)
// ---------------------------------------------------------------------------
// Per-node layer-1 partials in fp16: [gd_gene | gd_dis | gg_src | gg_dst]
__device__ __half g_Ph[42000000];

// ---------------------------------------------------------------------------
// helpers
// ---------------------------------------------------------------------------
__device__ __forceinline__ uint32_t smem_u32(const void* p){
    uint32_t a;
    asm("{ .reg .u64 t; cvta.to.shared.u64 t, %1; cvt.u32.u64 %0, t; }" : "=r"(a) : "l"(p));
    return a;
}
__device__ __forceinline__ void ldsm4(uint32_t* r, uint32_t addr){
    asm volatile("ldmatrix.sync.aligned.m8n8.x4.shared.b16 {%0,%1,%2,%3}, [%4];"
        : "=r"(r[0]), "=r"(r[1]), "=r"(r[2]), "=r"(r[3]) : "r"(addr));
}
__device__ __forceinline__ void ldsm4t(uint32_t* r, uint32_t addr){
    asm volatile("ldmatrix.sync.aligned.m8n8.x4.trans.shared.b16 {%0,%1,%2,%3}, [%4];"
        : "=r"(r[0]), "=r"(r[1]), "=r"(r[2]), "=r"(r[3]) : "r"(addr));
}
__device__ __forceinline__ void mma_f16(float* d, const uint32_t* a,
                                        uint32_t b0, uint32_t b1){
    asm volatile("mma.sync.aligned.m16n8k16.row.col.f32.f16.f16.f32 "
        "{%0,%1,%2,%3}, {%4,%5,%6,%7}, {%8,%9}, {%0,%1,%2,%3};"
        : "+f"(d[0]), "+f"(d[1]), "+f"(d[2]), "+f"(d[3])
        : "r"(a[0]), "r"(a[1]), "r"(a[2]), "r"(a[3]), "r"(b0), "r"(b1));
}

// XOR-swizzled byte offset inside a [128 rows x 128 fp16] tile (256B rows).
__device__ __forceinline__ uint32_t toff(int r, int kc){
    return (uint32_t)r * 256u + (uint32_t)((kc ^ (r & 7)) << 4);
}

// smem map: A 32KB | B 32KB
#define SM_A  0
#define SM_B  32768
#define SM_TOTAL 65536

// ---------------------------------------------------------------------------
// Kernel 1: single-pass fp16 GEMM (fp32 acc), 512 threads, 16 warps x 32x32.
// A staged once per tile; gene tiles loop parts 0,1,2; disease tiles part 3.
// B is converted fp32->fp16 on the fly from the ORIGINAL [k][n] weight layout
// (no prep kernel, no transpose); B fragments come via ldmatrix.trans.
// part: 0 = w1_gd[:128], 1 = w1_gg[:128], 2 = w1_gg[128:], 3 = w1_gd[128:]
// ---------------------------------------------------------------------------
__global__ void __launch_bounds__(512, 2)
gemm_tc_kernel(const float* __restrict__ zg, const float* __restrict__ zd,
               const float* __restrict__ w1_gd, const float* __restrict__ w1_gg,
               const float* __restrict__ b1_gd, const float* __restrict__ b1_gg,
               int n_gene, int n_dis)
{
    extern __shared__ char smem[];
    const uint32_t sb = smem_u32(smem);
    const int tid = threadIdx.x;

    const int tg = (n_gene + 127) >> 7;
    const size_t ng = (size_t)n_gene * H, nd = (size_t)n_dis * H;

    const int b = blockIdx.x;
    const bool isGene = (b < tg);
    const float* A = isGene ? zg : zd;
    const int M = isGene ? n_gene : n_dis;
    const int m0 = (isGene ? b : (b - tg)) << 7;
    const int nparts = isGene ? 3 : 1;

    // ---- stage A (fp32 -> fp16) once: 2048 16B chunks, 4 per thread ----
    #pragma unroll
    for (int i = 0; i < 4; i++) {
        int u = tid + 512 * i;
        int r = u >> 4, c8 = u & 15;
        float4 v0 = make_float4(0.f,0.f,0.f,0.f), v1 = v0;
        if (m0 + r < M) {
            const float* ap = &A[(size_t)(m0 + r) * H + c8 * 8];
            v0 = *(const float4*)ap;
            v1 = *(const float4*)(ap + 4);
        }
        __half2 h0 = __floats2half2_rn(v0.x, v0.y);
        __half2 h1 = __floats2half2_rn(v0.z, v0.w);
        __half2 h2 = __floats2half2_rn(v1.x, v1.y);
        __half2 h3 = __floats2half2_rn(v1.z, v1.w);
        uint4 pk = make_uint4(*(uint32_t*)&h0, *(uint32_t*)&h1,
                              *(uint32_t*)&h2, *(uint32_t*)&h3);
        *(uint4*)(smem + SM_A + toff(r, c8)) = pk;
    }

    const int lane = tid & 31, w = tid >> 5;
    const int wr = w >> 2, wc = w & 3;          // 4x4 warp grid, 32x32 tiles
    const int arow = wr * 32 + (lane & 15);
    const int akh  = lane >> 4;
    // B (trans) lane map: k-row = s*16 + (lane&15); n-col = wc*32 + np*16 + ((lane>>4)<<3)
    const int bkrow = lane & 15;
    const int bncol = wc * 32 + ((lane >> 4) << 3);
    const int rbase = m0 + wr * 32 + (lane >> 2);
    const int cbase = wc * 32 + (lane & 3) * 2;

    for (int p = 0; p < nparts; p++) {
        const int part = isGene ? p : 3;
        const float* bias = (part == 2) ? b1_gg : (part == 3) ? b1_gd : nullptr;
        const size_t outOff = (part == 0) ? 0
                            : (part == 1) ? (ng + nd)
                            : (part == 2) ? (ng + nd + ng)
                                          : ng;
        const float* Wsrc = (part == 0) ? w1_gd
                          : (part == 1) ? w1_gg
                          : (part == 2) ? (w1_gg + H * H)
                                        : (w1_gd + H * H);

        // ---- stage B (fp32 [k][n] -> fp16 smem [k][n], swizzled) ----
        #pragma unroll
        for (int i = 0; i < 4; i++) {
            int u = tid + 512 * i;
            int k = u >> 4, nc = u & 15;        // row k, 16B chunk nc (8 n)
            const float* wp = &Wsrc[(size_t)k * H + nc * 8];
            float4 v0 = *(const float4*)wp;
            float4 v1 = *(const float4*)(wp + 4);
            __half2 h0 = __floats2half2_rn(v0.x, v0.y);
            __half2 h1 = __floats2half2_rn(v0.z, v0.w);
            __half2 h2 = __floats2half2_rn(v1.x, v1.y);
            __half2 h3 = __floats2half2_rn(v1.z, v1.w);
            uint4 pk = make_uint4(*(uint32_t*)&h0, *(uint32_t*)&h1,
                                  *(uint32_t*)&h2, *(uint32_t*)&h3);
            *(uint4*)(smem + SM_B + toff(k, nc)) = pk;
        }
        __syncthreads();

        // ---- compute: 32x32 warp tile ----
        float acc[2][4][4];
        #pragma unroll
        for (int mt = 0; mt < 2; mt++)
            #pragma unroll
            for (int nt = 0; nt < 4; nt++)
                #pragma unroll
                for (int q = 0; q < 4; q++) acc[mt][nt][q] = 0.f;

        #pragma unroll
        for (int s = 0; s < 8; s++) {
            uint32_t afr[2][4];
            #pragma unroll
            for (int mt = 0; mt < 2; mt++)
                ldsm4(afr[mt], sb + SM_A + toff(arow + mt * 16, 2 * s + akh));

            uint32_t bfr[2][4];
            #pragma unroll
            for (int np = 0; np < 2; np++)
                ldsm4t(bfr[np], sb + SM_B
                       + toff(s * 16 + bkrow, (bncol + np * 16) >> 3));

            #pragma unroll
            for (int mt = 0; mt < 2; mt++)
                #pragma unroll
                for (int nt = 0; nt < 4; nt++)
                    mma_f16(acc[mt][nt], afr[mt],
                            bfr[nt >> 1][(nt & 1) * 2], bfr[nt >> 1][(nt & 1) * 2 + 1]);
        }

        // ---- writeout (fp16) ----
        #pragma unroll
        for (int mt = 0; mt < 2; mt++) {
            #pragma unroll
            for (int nt = 0; nt < 4; nt++) {
                int n = cbase + nt * 8;
                float bx = 0.f, by = 0.f;
                if (bias) { float2 bv = *(const float2*)&bias[n]; bx = bv.x; by = bv.y; }
                int rr0 = rbase + mt * 16;
                int rr1 = rr0 + 8;
                if (rr0 < M) {
                    __half2 o0 = __floats2half2_rn(acc[mt][nt][0] + bx, acc[mt][nt][1] + by);
                    *(__half2*)&g_Ph[outOff + (size_t)rr0 * H + n] = o0;
                }
                if (rr1 < M) {
                    __half2 o1 = __floats2half2_rn(acc[mt][nt][2] + bx, acc[mt][nt][3] + by);
                    *(__half2*)&g_Ph[outOff + (size_t)rr1 * H + n] = o1;
                }
            }
        }
        if (p + 1 < nparts) __syncthreads();
    }
}

// ---------------------------------------------------------------------------
// Kernel 2: per-edge combine on fp16 partials. One warp per edge, x2 ILP.
// ---------------------------------------------------------------------------
__global__ void __launch_bounds__(256)
edge_decode_kernel(const int* __restrict__ edges_gd, const int* __restrict__ edges_gg,
                   const float* __restrict__ w2_gd, const float* __restrict__ b2_gd,
                   const float* __restrict__ w2_gg, const float* __restrict__ b2_gg,
                   float* __restrict__ out, int E, int n_gene, int n_dis)
{
    const int rel = blockIdx.y;
    const size_t ng = (size_t)n_gene * H;
    const size_t nd = (size_t)n_dis * H;

    const int*   edges = rel ? edges_gg : edges_gd;
    const __half* Psrc = rel ? (g_Ph + ng + nd)      : g_Ph;
    const __half* Pdst = rel ? (g_Ph + ng + nd + ng) : (g_Ph + ng);
    const float* w2    = rel ? w2_gg : w2_gd;
    const float  b2    = (rel ? b2_gg : b2_gd)[0];
    float* o = out + (size_t)rel * E;

    const int lane   = threadIdx.x & 31;
    const int warp   = (blockIdx.x * blockDim.x + threadIdx.x) >> 5;
    const int nwarps = (gridDim.x * blockDim.x) >> 5;

    const float4 w = *(const float4*)&w2[lane * 4];

    for (int e = warp; e < E; e += 2 * nwarps) {
        const int e1 = e + nwarps;
        const bool has2 = e1 < E;

        const int s0 = edges[e], d0 = edges[E + e];
        uint2 ua0 = *(const uint2*)&Psrc[(size_t)s0 * H + lane * 4];
        uint2 ub0 = *(const uint2*)&Pdst[(size_t)d0 * H + lane * 4];

        uint2 ua1 = make_uint2(0u, 0u), ub1 = ua1;
        if (has2) {
            const int s1 = edges[e1], d1 = edges[E + e1];
            ua1 = *(const uint2*)&Psrc[(size_t)s1 * H + lane * 4];
            ub1 = *(const uint2*)&Pdst[(size_t)d1 * H + lane * 4];
        }

        float2 fa0 = __half22float2(*(__half2*)&ua0.x);
        float2 fa1 = __half22float2(*(__half2*)&ua0.y);
        float2 fb0 = __half22float2(*(__half2*)&ub0.x);
        float2 fb1 = __half22float2(*(__half2*)&ub0.y);
        float sum0;
        sum0  = fmaxf(fa0.x + fb0.x, 0.f) * w.x;
        sum0 += fmaxf(fa0.y + fb0.y, 0.f) * w.y;
        sum0 += fmaxf(fa1.x + fb1.x, 0.f) * w.z;
        sum0 += fmaxf(fa1.y + fb1.y, 0.f) * w.w;
        #pragma unroll
        for (int off = 16; off; off >>= 1)
            sum0 += __shfl_xor_sync(0xFFFFFFFFu, sum0, off);
        if (lane == 0) o[e] = sum0 + b2;

        if (has2) {
            float2 ga0 = __half22float2(*(__half2*)&ua1.x);
            float2 ga1 = __half22float2(*(__half2*)&ua1.y);
            float2 gb0 = __half22float2(*(__half2*)&ub1.x);
            float2 gb1 = __half22float2(*(__half2*)&ub1.y);
            float sum1;
            sum1  = fmaxf(ga0.x + gb0.x, 0.f) * w.x;
            sum1 += fmaxf(ga0.y + gb0.y, 0.f) * w.y;
            sum1 += fmaxf(ga1.x + gb1.x, 0.f) * w.z;
            sum1 += fmaxf(ga1.y + gb1.y, 0.f) * w.w;
            #pragma unroll
            for (int off = 16; off; off >>= 1)
                sum1 += __shfl_xor_sync(0xFFFFFFFFu, sum1, off);
            if (lane == 0) o[e1] = sum1 + b2;
        }
    }
}

// ---------------------------------------------------------------------------
extern "C" void kernel_launch(void* const* d_in, const int* in_sizes, int n_in,
                              void* d_out, int out_size)
{
    const float* z_gene = (const float*)d_in[0];
    const float* z_dis  = (const float*)d_in[1];
    const int*   e_gd   = (const int*)  d_in[2];
    const int*   e_gg   = (const int*)  d_in[3];
    const float* w1_gd  = (const float*)d_in[4];
    const float* b1_gd  = (const float*)d_in[5];
    const float* w2_gd  = (const float*)d_in[6];
    const float* b2_gd  = (const float*)d_in[7];
    const float* w1_gg  = (const float*)d_in[8];
    const float* b1_gg  = (const float*)d_in[9];
    const float* w2_gg  = (const float*)d_in[10];
    const float* b2_gg  = (const float*)d_in[11];

    const int n_gene = in_sizes[0] / H;
    const int n_dis  = in_sizes[1] / H;
    const int E      = in_sizes[2] / 2;

    static bool init_done = false;
    if (!init_done) {
        cudaFuncSetAttribute(gemm_tc_kernel,
                             cudaFuncAttributeMaxDynamicSharedMemorySize, SM_TOTAL);
        init_done = true;
    }

    const int tg = (n_gene + 127) >> 7;
    const int td = (n_dis + 127) >> 7;
    gemm_tc_kernel<<<tg + td, 512, SM_TOTAL>>>(z_gene, z_dis, w1_gd, w1_gg,
                                               b1_gd, b1_gg, n_gene, n_dis);

    dim3 egrid(1184, 2);
    edge_decode_kernel<<<egrid, 256>>>(e_gd, e_gg, w2_gd, b2_gd, w2_gg, b2_gg,
                                       (float*)d_out, E, n_gene, n_dis);
}

// round 16
// speedup vs baseline: 1.8083x; 1.2512x over previous
#include <cuda_runtime.h>
#include <cuda_fp16.h>
#include <cstdint>

#define H 128

// ---------------------------------------------------------------------------
// Global scratch (no allocations allowed)
// ---------------------------------------------------------------------------
// Per-node layer-1 partials in fp16: [gd_gene | gd_dis | gg_src | gg_dst]
__device__ __half g_Ph[42000000];
// fp16 weights (rounded), transposed: [part][n][k]
// part: 0 = w1_gd[:128], 1 = w1_gg[:128], 2 = w1_gg[128:], 3 = w1_gd[128:]
__device__ __half g_Wh[4 * H * H];

// ---------------------------------------------------------------------------
// helpers
// ---------------------------------------------------------------------------
__device__ __forceinline__ uint32_t smem_u32(const void* p){
    uint32_t a;
    asm("{ .reg .u64 t; cvta.to.shared.u64 t, %1; cvt.u32.u64 %0, t; }" : "=r"(a) : "l"(p));
    return a;
}
__device__ __forceinline__ void ldsm4(uint32_t* r, uint32_t addr){
    asm volatile("ldmatrix.sync.aligned.m8n8.x4.shared.b16 {%0,%1,%2,%3}, [%4];"
        : "=r"(r[0]), "=r"(r[1]), "=r"(r[2]), "=r"(r[3]) : "r"(addr));
}
__device__ __forceinline__ void mma_f16(float* d, const uint32_t* a,
                                        uint32_t b0, uint32_t b1){
    asm volatile("mma.sync.aligned.m16n8k16.row.col.f32.f16.f16.f32 "
        "{%0,%1,%2,%3}, {%4,%5,%6,%7}, {%8,%9}, {%0,%1,%2,%3};"
        : "+f"(d[0]), "+f"(d[1]), "+f"(d[2]), "+f"(d[3])
        : "r"(a[0]), "r"(a[1]), "r"(a[2]), "r"(a[3]), "r"(b0), "r"(b1));
}

// XOR-swizzled byte offset inside a [128 rows x 128 fp16] tile (256B rows).
__device__ __forceinline__ uint32_t toff(int r, int kc){
    return (uint32_t)r * 256u + (uint32_t)((kc ^ (r & 7)) << 4);
}

// smem map: A 32KB | B 32KB
#define SM_A  0
#define SM_B  32768
#define SM_TOTAL 65536

// ---------------------------------------------------------------------------
// Kernel 0: round+transpose the four 128x128 W blocks -> fp16, [n][k]
// ---------------------------------------------------------------------------
__global__ void prep_w_kernel(const float* __restrict__ w1_gd,
                              const float* __restrict__ w1_gg)
{
    int idx = blockIdx.x * blockDim.x + threadIdx.x;  // 4*128*128
    if (idx >= 4 * H * H) return;
    int part = idx >> 14;
    int n = (idx >> 7) & 127;
    int k = idx & 127;
    const float* Wsrc = (part == 0) ? w1_gd
                      : (part == 1) ? w1_gg
                      : (part == 2) ? (w1_gg + H * H)
                                    : (w1_gd + H * H);
    g_Wh[((size_t)part * H + n) * H + k] = __float2half_rn(Wsrc[k * H + n]);
}

// ---------------------------------------------------------------------------
// Kernel 1: single-pass fp16 GEMM (fp32 acc), 512 threads, 16 warps x 32x32.
// A staged once; gene tiles loop parts 0,1,2; disease tiles part 3.
// (bit-identical to the 137.7us round-8 kernel)
// ---------------------------------------------------------------------------
__global__ void __launch_bounds__(512, 2)
gemm_tc_kernel(const float* __restrict__ zg, const float* __restrict__ zd,
               const float* __restrict__ b1_gd, const float* __restrict__ b1_gg,
               int n_gene, int n_dis)
{
    extern __shared__ char smem[];
    const uint32_t sb = smem_u32(smem);
    const int tid = threadIdx.x;

    const int tg = (n_gene + 127) >> 7;
    const size_t ng = (size_t)n_gene * H, nd = (size_t)n_dis * H;

    const int b = blockIdx.x;
    const bool isGene = (b < tg);
    const float* A = isGene ? zg : zd;
    const int M = isGene ? n_gene : n_dis;
    const int m0 = (isGene ? b : (b - tg)) << 7;
    const int nparts = isGene ? 3 : 1;

    // ---- stage A (fp32 -> fp16) once: 2048 16B chunks, 4 per thread ----
    #pragma unroll
    for (int i = 0; i < 4; i++) {
        int u = tid + 512 * i;
        int r = u >> 4, c8 = u & 15;
        float4 v0 = make_float4(0.f,0.f,0.f,0.f), v1 = v0;
        if (m0 + r < M) {
            const float* ap = &A[(size_t)(m0 + r) * H + c8 * 8];
            v0 = *(const float4*)ap;
            v1 = *(const float4*)(ap + 4);
        }
        __half2 h0 = __floats2half2_rn(v0.x, v0.y);
        __half2 h1 = __floats2half2_rn(v0.z, v0.w);
        __half2 h2 = __floats2half2_rn(v1.x, v1.y);
        __half2 h3 = __floats2half2_rn(v1.z, v1.w);
        uint4 pk = make_uint4(*(uint32_t*)&h0, *(uint32_t*)&h1,
                              *(uint32_t*)&h2, *(uint32_t*)&h3);
        *(uint4*)(smem + SM_A + toff(r, c8)) = pk;
    }

    const int lane = tid & 31, w = tid >> 5;
    const int wr = w >> 2, wc = w & 3;          // 4x4 warp grid, 32x32 tiles
    const int arow = wr * 32 + (lane & 15);
    const int akh  = lane >> 4;
    const int brow = wc * 32 + (lane & 7) + ((lane >> 4) << 3);
    const int bkh  = (lane >> 3) & 1;
    const int rbase = m0 + wr * 32 + (lane >> 2);
    const int cbase = wc * 32 + (lane & 3) * 2;

    for (int p = 0; p < nparts; p++) {
        const int part = isGene ? p : 3;
        const float* bias = (part == 2) ? b1_gg : (part == 3) ? b1_gd : nullptr;
        const size_t outOff = (part == 0) ? 0
                            : (part == 1) ? (ng + nd)
                            : (part == 2) ? (ng + nd + ng)
                                          : ng;

        // ---- stage B for this part: 2048 chunks, 4 per thread ----
        {
            const uint4* bp = (const uint4*)(g_Wh + (size_t)part * H * H);
            #pragma unroll
            for (int i = 0; i < 4; i++) {
                int u = tid + 512 * i;
                int r = u >> 4, kc = u & 15;
                *(uint4*)(smem + SM_B + toff(r, kc)) = bp[u];
            }
        }
        __syncthreads();

        // ---- compute: 32x32 warp tile ----
        float acc[2][4][4];
        #pragma unroll
        for (int mt = 0; mt < 2; mt++)
            #pragma unroll
            for (int nt = 0; nt < 4; nt++)
                #pragma unroll
                for (int q = 0; q < 4; q++) acc[mt][nt][q] = 0.f;

        #pragma unroll
        for (int s = 0; s < 8; s++) {
            uint32_t afr[2][4];
            #pragma unroll
            for (int mt = 0; mt < 2; mt++)
                ldsm4(afr[mt], sb + SM_A + toff(arow + mt * 16, 2 * s + akh));

            uint32_t bfr[2][4];
            #pragma unroll
            for (int np = 0; np < 2; np++)
                ldsm4(bfr[np], sb + SM_B + toff(brow + np * 16, 2 * s + bkh));

            #pragma unroll
            for (int mt = 0; mt < 2; mt++)
                #pragma unroll
                for (int nt = 0; nt < 4; nt++)
                    mma_f16(acc[mt][nt], afr[mt],
                            bfr[nt >> 1][(nt & 1) * 2], bfr[nt >> 1][(nt & 1) * 2 + 1]);
        }

        // ---- writeout (fp16) ----
        #pragma unroll
        for (int mt = 0; mt < 2; mt++) {
            #pragma unroll
            for (int nt = 0; nt < 4; nt++) {
                int n = cbase + nt * 8;
                float bx = 0.f, by = 0.f;
                if (bias) { float2 bv = *(const float2*)&bias[n]; bx = bv.x; by = bv.y; }
                int rr0 = rbase + mt * 16;
                int rr1 = rr0 + 8;
                if (rr0 < M) {
                    __half2 o0 = __floats2half2_rn(acc[mt][nt][0] + bx, acc[mt][nt][1] + by);
                    *(__half2*)&g_Ph[outOff + (size_t)rr0 * H + n] = o0;
                }
                if (rr1 < M) {
                    __half2 o1 = __floats2half2_rn(acc[mt][nt][2] + bx, acc[mt][nt][3] + by);
                    *(__half2*)&g_Ph[outOff + (size_t)rr1 * H + n] = o1;
                }
            }
        }
        if (p + 1 < nparts) __syncthreads();
    }
}

// ---------------------------------------------------------------------------
// Kernel 2: per-edge combine. HALF-WARP per edge (16 lanes x uint4 = 256B
// row), half2 add+relu, fp32 dot, 4-step butterfly. x2 ILP -> 4 edges/warp/iter.
// ---------------------------------------------------------------------------
__device__ __forceinline__ float edot8(uint4 ua, uint4 ub,
                                       float4 w0, float4 w1){
    const __half2 z = __half2half2(__ushort_as_half(0));
    __half2 h0 = __hmax2(__hadd2(*(__half2*)&ua.x, *(__half2*)&ub.x), z);
    __half2 h1 = __hmax2(__hadd2(*(__half2*)&ua.y, *(__half2*)&ub.y), z);
    __half2 h2 = __hmax2(__hadd2(*(__half2*)&ua.z, *(__half2*)&ub.z), z);
    __half2 h3 = __hmax2(__hadd2(*(__half2*)&ua.w, *(__half2*)&ub.w), z);
    float2 f0 = __half22float2(h0);
    float2 f1 = __half22float2(h1);
    float2 f2 = __half22float2(h2);
    float2 f3 = __half22float2(h3);
    float s;
    s  = f0.x * w0.x;
    s  = fmaf(f0.y, w0.y, s);
    s  = fmaf(f1.x, w0.z, s);
    s  = fmaf(f1.y, w0.w, s);
    s  = fmaf(f2.x, w1.x, s);
    s  = fmaf(f2.y, w1.y, s);
    s  = fmaf(f3.x, w1.z, s);
    s  = fmaf(f3.y, w1.w, s);
    return s;
}

__global__ void __launch_bounds__(256)
edge_decode_kernel(const int* __restrict__ edges_gd, const int* __restrict__ edges_gg,
                   const float* __restrict__ w2_gd, const float* __restrict__ b2_gd,
                   const float* __restrict__ w2_gg, const float* __restrict__ b2_gg,
                   float* __restrict__ out, int E, int n_gene, int n_dis)
{
    const int rel = blockIdx.y;
    const size_t ng = (size_t)n_gene * H;
    const size_t nd = (size_t)n_dis * H;

    const int*   edges = rel ? edges_gg : edges_gd;
    const __half* Psrc = rel ? (g_Ph + ng + nd)      : g_Ph;
    const __half* Pdst = rel ? (g_Ph + ng + nd + ng) : (g_Ph + ng);
    const float* w2    = rel ? w2_gg : w2_gd;
    const float  b2    = (rel ? b2_gg : b2_gd)[0];
    float* o = out + (size_t)rel * E;

    const int lane   = threadIdx.x & 31;
    const int warp   = (blockIdx.x * blockDim.x + threadIdx.x) >> 5;
    const int nwarps = (gridDim.x * blockDim.x) >> 5;
    const int hl  = lane >> 4;       // half-warp id (0/1)
    const int sub = lane & 15;       // lane within half-warp

    const float4 w0 = *(const float4*)&w2[sub * 8];
    const float4 w1 = *(const float4*)&w2[sub * 8 + 4];

    const uint4 zero4 = make_uint4(0u, 0u, 0u, 0u);

    for (int base = 2 * warp; base < E; base += 4 * nwarps) {
        const int eA = base + hl;
        const int eB = base + 2 * nwarps + hl;
        const bool hasA = eA < E;
        const bool hasB = eB < E;

        uint4 a0 = zero4, b0 = zero4, a1 = zero4, b1 = zero4;
        if (hasA) {
            const int s = edges[eA], d = edges[E + eA];
            a0 = *(const uint4*)&Psrc[(size_t)s * H + sub * 8];
            b0 = *(const uint4*)&Pdst[(size_t)d * H + sub * 8];
        }
        if (hasB) {
            const int s = edges[eB], d = edges[E + eB];
            a1 = *(const uint4*)&Psrc[(size_t)s * H + sub * 8];
            b1 = *(const uint4*)&Pdst[(size_t)d * H + sub * 8];
        }

        float sA = edot8(a0, b0, w0, w1);
        float sB = edot8(a1, b1, w0, w1);

        // butterfly within each 16-lane half (xor offsets < 16)
        #pragma unroll
        for (int off = 8; off; off >>= 1) {
            sA += __shfl_xor_sync(0xFFFFFFFFu, sA, off);
            sB += __shfl_xor_sync(0xFFFFFFFFu, sB, off);
        }

        if (sub == 0) {
            if (hasA) o[eA] = sA + b2;
            if (hasB) o[eB] = sB + b2;
        }
    }
}

// ---------------------------------------------------------------------------
extern "C" void kernel_launch(void* const* d_in, const int* in_sizes, int n_in,
                              void* d_out, int out_size)
{
    const float* z_gene = (const float*)d_in[0];
    const float* z_dis  = (const float*)d_in[1];
    const int*   e_gd   = (const int*)  d_in[2];
    const int*   e_gg   = (const int*)  d_in[3];
    const float* w1_gd  = (const float*)d_in[4];
    const float* b1_gd  = (const float*)d_in[5];
    const float* w2_gd  = (const float*)d_in[6];
    const float* b2_gd  = (const float*)d_in[7];
    const float* w1_gg  = (const float*)d_in[8];
    const float* b1_gg  = (const float*)d_in[9];
    const float* w2_gg  = (const float*)d_in[10];
    const float* b2_gg  = (const float*)d_in[11];

    const int n_gene = in_sizes[0] / H;
    const int n_dis  = in_sizes[1] / H;
    const int E      = in_sizes[2] / 2;

    static bool init_done = false;
    if (!init_done) {
        cudaFuncSetAttribute(gemm_tc_kernel,
                             cudaFuncAttributeMaxDynamicSharedMemorySize, SM_TOTAL);
        init_done = true;
    }

    prep_w_kernel<<<(4 * H * H + 255) / 256, 256>>>(w1_gd, w1_gg);

    const int tg = (n_gene + 127) >> 7;
    const int td = (n_dis + 127) >> 7;
    gemm_tc_kernel<<<tg + td, 512, SM_TOTAL>>>(z_gene, z_dis, b1_gd, b1_gg,
                                               n_gene, n_dis);

    dim3 egrid(1184, 2);
    edge_decode_kernel<<<egrid, 256>>>(e_gd, e_gg, w2_gd, b2_gd, w2_gg, b2_gg,
                                       (float*)d_out, E, n_gene, n_dis);
}